// round 6
// baseline (speedup 1.0000x reference)
#include <cuda_runtime.h>
#include <math.h>
#include <stdint.h>

// Problem constants
#define NSEQ 512       // B*S
#define BHD 384        // BH
#define NHD 8          // heads
#define HDD 48         // head dim
#define TTOT 16        // T = P + S_C
#define PPRE 4         // P
#define SCDEC 12       // S_C
#define LLAY 4         // L
#define VOC 258
#define HIN 1024
#define FFD 1536
#define EOS_ID 257
#define SCALE_F 0.14433756729740643f   // 1/sqrt(48)

// ---------------- scratch (device globals; no runtime allocation) ----------------
__device__ float g_xout[NSEQ * TTOT * BHD];            // (N,16,384)
__device__ float g_kc[LLAY][NSEQ * TTOT * BHD];        // per-layer K cache
__device__ float g_vc[LLAY][NSEQ * TTOT * BHD];        // per-layer V cache
__device__ float g_xi[NSEQ * 4 * BHD];                 // working residual stream
__device__ float g_h[NSEQ * 4 * BHD];                  // rms output
__device__ float g_q[NSEQ * 4 * BHD];                  // compact Q (M,384)
__device__ float g_o[NSEQ * 4 * BHD];                  // attention output
__device__ float g_t[NSEQ * 4 * FFD];                  // ffn intermediate / lm input
__device__ float g_wqkv[LLAY * BHD * 3 * BHD];         // concatenated QKV weights
__device__ int   g_fin[NSEQ];

// ---------------- tf32 helpers ----------------
__device__ __forceinline__ void split_tf32(float x, uint32_t& hi, uint32_t& lo) {
    uint32_t h = __float_as_uint(x) & 0xffffe000u;
    float r = x - __uint_as_float(h);
    uint32_t l;
    asm("cvt.rna.tf32.f32 %0, %1;" : "=r"(l) : "f"(r));
    hi = h; lo = l;
}

__device__ __forceinline__ void mma8(float* d, const uint32_t* a, uint32_t b0, uint32_t b1) {
    asm volatile(
        "mma.sync.aligned.m16n8k8.row.col.f32.tf32.tf32.f32 "
        "{%0,%1,%2,%3},{%4,%5,%6,%7},{%8,%9},{%0,%1,%2,%3};\n"
        : "+f"(d[0]), "+f"(d[1]), "+f"(d[2]), "+f"(d[3])
        : "r"(a[0]), "r"(a[1]), "r"(a[2]), "r"(a[3]), "r"(b0), "r"(b1));
}

// epilogue modes
#define EPI_STORE 0
#define EPI_ACC   1
#define EPI_GELU  2
#define EPI_QKV   3

__device__ __forceinline__ void qkv_write(int m, int gc, float v, int lqShift, int pos, int layer) {
    int n  = m >> lqShift;
    int qi = m & ((1 << lqShift) - 1);
    if (gc < BHD) {
        g_q[(size_t)m * BHD + gc] = v;
    } else {
        int tp = pos + qi;
        size_t base = ((size_t)n * TTOT + tp) * BHD;
        if (gc < 2 * BHD) g_kc[layer][base + gc - BHD] = v;
        else              g_vc[layer][base + gc - 2 * BHD] = v;
    }
}

// ---------------- tf32 MMA GEMM: C[M,N] (+)= A[M,K] @ B[K,N] ----------------
// 3xTF32 decomposition; hi/lo split done ONCE at staging time into shared.
// Two-stage software pipeline: global loads for tile i+1 issued during compute
// of tile i. 8 warps / 256 threads. BM=WM*16, BN=WN*NT*8, BK=16.
template<int BM, int BN, int WM, int WN, int NT, int MODE>
__global__ __launch_bounds__(256) void mma_gemm(
    const float* __restrict__ A, int lda,
    const float* __restrict__ B, int ldb,
    float* __restrict__ C, int ldc,
    int M, int N, int K,
    int lqShift, int pos, int layer)
{
    static_assert(WM * WN == 8, "8 warps");
    static_assert(WM * 16 == BM, "BM");
    static_assert(WN * NT * 8 == BN, "BN");

    __shared__ uint32_t AsH[BM][20], AsL[BM][20];
    __shared__ uint32_t BsH[16][BN + 4], BsL[16][BN + 4];

    const int t = threadIdx.x;
    const int lane = t & 31;
    const int w = t >> 5;
    const int wm = w % WM;
    const int wn = w / WM;
    const int gid = lane >> 2;   // 0..7
    const int tig = lane & 3;    // 0..3

    const int m0 = blockIdx.y * BM;
    const int n0 = blockIdx.x * BN;
    // float4 B loads legal only if row starts stay 16B-aligned and tile in-bounds
    const bool vecB = ((ldb & 3) == 0) && (n0 + BN <= N);

    // staging thread roles
    const bool aAct = (t < 4 * BM);
    const int am = t >> 2;               // 0..BM-1 (when aAct)
    const int ak = (t & 3) * 4;
    const bool bAct = (t < 4 * BN);
    const int bk = t / (BN / 4);         // 0..15 (when bAct)
    const int bn = (t % (BN / 4)) * 4;

    float acc[NT][4];
    #pragma unroll
    for (int i = 0; i < NT; i++)
        #pragma unroll
        for (int j = 0; j < 4; j++) acc[i][j] = 0.f;

    float aR0=0.f, aR1=0.f, aR2=0.f, aR3=0.f;
    float bR0=0.f, bR1=0.f, bR2=0.f, bR3=0.f;

    const int kIters = K / 16;

    // prologue: load tile 0 into regs
    if (aAct) {
        float4 v = *reinterpret_cast<const float4*>(A + (size_t)(m0 + am) * lda + ak);
        aR0 = v.x; aR1 = v.y; aR2 = v.z; aR3 = v.w;
    }
    if (bAct) {
        const float* brow = B + (size_t)bk * ldb;
        if (vecB) {
            float4 v = *reinterpret_cast<const float4*>(brow + n0 + bn);
            bR0 = v.x; bR1 = v.y; bR2 = v.z; bR3 = v.w;
        } else {
            int c0 = n0 + bn;
            bR0 = (c0 + 0 < N) ? brow[c0 + 0] : 0.f;
            bR1 = (c0 + 1 < N) ? brow[c0 + 1] : 0.f;
            bR2 = (c0 + 2 < N) ? brow[c0 + 2] : 0.f;
            bR3 = (c0 + 3 < N) ? brow[c0 + 3] : 0.f;
        }
    }

    for (int it = 0; it < kIters; ++it) {
        // store stage (split once per element)
        if (aAct) {
            uint32_t h, l;
            split_tf32(aR0, h, l); AsH[am][ak + 0] = h; AsL[am][ak + 0] = l;
            split_tf32(aR1, h, l); AsH[am][ak + 1] = h; AsL[am][ak + 1] = l;
            split_tf32(aR2, h, l); AsH[am][ak + 2] = h; AsL[am][ak + 2] = l;
            split_tf32(aR3, h, l); AsH[am][ak + 3] = h; AsL[am][ak + 3] = l;
        }
        if (bAct) {
            uint32_t h, l;
            split_tf32(bR0, h, l); BsH[bk][bn + 0] = h; BsL[bk][bn + 0] = l;
            split_tf32(bR1, h, l); BsH[bk][bn + 1] = h; BsL[bk][bn + 1] = l;
            split_tf32(bR2, h, l); BsH[bk][bn + 2] = h; BsL[bk][bn + 2] = l;
            split_tf32(bR3, h, l); BsH[bk][bn + 3] = h; BsL[bk][bn + 3] = l;
        }
        __syncthreads();

        // prefetch next tile
        if (it + 1 < kIters) {
            const int k0n = (it + 1) * 16;
            if (aAct) {
                float4 v = *reinterpret_cast<const float4*>(A + (size_t)(m0 + am) * lda + k0n + ak);
                aR0 = v.x; aR1 = v.y; aR2 = v.z; aR3 = v.w;
            }
            if (bAct) {
                const float* brow = B + (size_t)(k0n + bk) * ldb;
                if (vecB) {
                    float4 v = *reinterpret_cast<const float4*>(brow + n0 + bn);
                    bR0 = v.x; bR1 = v.y; bR2 = v.z; bR3 = v.w;
                } else {
                    int c0 = n0 + bn;
                    bR0 = (c0 + 0 < N) ? brow[c0 + 0] : 0.f;
                    bR1 = (c0 + 1 < N) ? brow[c0 + 1] : 0.f;
                    bR2 = (c0 + 2 < N) ? brow[c0 + 2] : 0.f;
                    bR3 = (c0 + 3 < N) ? brow[c0 + 3] : 0.f;
                }
            }
        }

        // compute from shared (pure LDS + MMA)
        #pragma unroll
        for (int kt = 0; kt < 2; kt++) {
            const int kk = kt * 8;
            const int arow = wm * 16 + gid;
            uint32_t ah[4], al[4];
            ah[0] = AsH[arow][kk + tig];     al[0] = AsL[arow][kk + tig];
            ah[1] = AsH[arow + 8][kk + tig]; al[1] = AsL[arow + 8][kk + tig];
            ah[2] = AsH[arow][kk + tig + 4]; al[2] = AsL[arow][kk + tig + 4];
            ah[3] = AsH[arow + 8][kk + tig + 4]; al[3] = AsL[arow + 8][kk + tig + 4];

            #pragma unroll
            for (int nt = 0; nt < NT; nt++) {
                const int cb = wn * NT * 8 + nt * 8 + gid;
                uint32_t bh0 = BsH[kk + tig][cb];
                uint32_t bh1 = BsH[kk + tig + 4][cb];
                uint32_t bl0 = BsL[kk + tig][cb];
                uint32_t bl1 = BsL[kk + tig + 4][cb];
                // small terms first, big term last (matches round-5 numerics)
                mma8(acc[nt], al, bh0, bh1);
                mma8(acc[nt], ah, bl0, bl1);
                mma8(acc[nt], ah, bh0, bh1);
            }
        }
        __syncthreads();
    }

    // epilogue
    #pragma unroll
    for (int nt = 0; nt < NT; nt++) {
        const int c0 = n0 + wn * NT * 8 + nt * 8 + tig * 2;
        const int r0 = m0 + wm * 16 + gid;
        const int r1 = r0 + 8;
        #pragma unroll
        for (int j = 0; j < 4; j++) {
            int r = (j < 2) ? r0 : r1;
            int c = c0 + (j & 1);
            float v = acc[nt][j];
            if (MODE == EPI_QKV) {
                qkv_write(r, c, v, lqShift, pos, layer);
            } else {
                if (c < N) {
                    size_t off = (size_t)r * (size_t)ldc + c;
                    if (MODE == EPI_GELU) {
                        v = 0.5f * v * (1.f + erff(v * 0.70710678118654752f));
                        C[off] = v;
                    } else if (MODE == EPI_ACC) {
                        C[off] += v;
                    } else {
                        C[off] = v;
                    }
                }
            }
        }
    }
}

// ---------------- small helper kernels ----------------

__global__ void init_fin_k() {
    int i = blockIdx.x * blockDim.x + threadIdx.x;
    if (i < NSEQ) g_fin[i] = 0;
}

__global__ void concat_k(const float* __restrict__ Wq,
                         const float* __restrict__ Wk,
                         const float* __restrict__ Wv) {
    int idx = blockIdx.x * blockDim.x + threadIdx.x;
    const int per = BHD * 3 * BHD;
    if (idx >= LLAY * per) return;
    int l = idx / per;
    int r = idx - l * per;
    int k = r / (3 * BHD);
    int j = r - k * (3 * BHD);
    float v;
    int base = l * BHD * BHD + k * BHD;
    if (j < BHD)            v = Wq[base + j];
    else if (j < 2 * BHD)   v = Wk[base + j - BHD];
    else                    v = Wv[base + j - 2 * BHD];
    g_wqkv[idx] = v;
}

// RMS norm: one block per row (128 threads), 384 cols
__global__ void rms_k(const float* __restrict__ in, const float* __restrict__ gain,
                      float* __restrict__ out) {
    int row = blockIdx.x;
    int t = threadIdx.x;
    const float* r = in + (size_t)row * BHD;
    float s = 0.f;
    for (int c = t; c < BHD; c += 128) { float v = r[c]; s += v * v; }
    for (int o = 16; o > 0; o >>= 1) s += __shfl_xor_sync(0xffffffffu, s, o);
    __shared__ float sh[4];
    if ((t & 31) == 0) sh[t >> 5] = s;
    __syncthreads();
    __shared__ float sc;
    if (t == 0) {
        float tot = sh[0] + sh[1] + sh[2] + sh[3];
        sc = rsqrtf(tot / (float)BHD + 1e-5f);
    }
    __syncthreads();
    float scale = sc;
    float* wp = out + (size_t)row * BHD;
    for (int c = t; c < BHD; c += 128) wp[c] = r[c] * scale * gain[c];
}

// copy xi from x_out
__global__ void copy_xi_k(int Lq, int srcT, int total) {
    int idx = blockIdx.x * blockDim.x + threadIdx.x;
    if (idx >= total) return;
    int m = idx / BHD;
    int c = idx - m * BHD;
    int n = m / Lq;
    int qi = m - n * Lq;
    g_xi[idx] = g_xout[(size_t)n * TTOT * BHD + (size_t)(srcT + qi) * BHD + c];
}

// attention: one block per sequence, 8 warps; warp handles (qi,head) pairs
__global__ void attn_k(int l, int Lq, int pos, int causal) {
    int n = blockIdx.x;
    int warp = threadIdx.x >> 5;
    int lane = threadIdx.x & 31;
    int nk = pos + Lq;
    int npairs = NHD * Lq;
    __shared__ float ps[8][16];
    const float* kc = g_kc[l] + (size_t)n * TTOT * BHD;
    const float* vc = g_vc[l] + (size_t)n * TTOT * BHD;
    for (int pair = warp; pair < npairs; pair += 8) {
        int qi = pair >> 3;
        int hh = pair & 7;
        int m = n * Lq + qi;
        const float* q = g_q + (size_t)m * BHD + hh * HDD;
        float s = -3.402823466e38f;
        if (lane < nk) {
            const float* kr = kc + (size_t)lane * BHD + hh * HDD;
            float a = 0.f;
            #pragma unroll
            for (int d = 0; d < HDD; d++) a += q[d] * kr[d];
            s = a * SCALE_F;
            if (causal && lane > pos + qi) s = -1e30f;
        }
        float mx = s;
        #pragma unroll
        for (int o = 16; o > 0; o >>= 1) mx = fmaxf(mx, __shfl_xor_sync(0xffffffffu, mx, o));
        float e = (lane < nk) ? expf(s - mx) : 0.f;
        float den = e;
        #pragma unroll
        for (int o = 16; o > 0; o >>= 1) den += __shfl_xor_sync(0xffffffffu, den, o);
        float p = e / den;
        if (lane < 16) ps[warp][lane] = (lane < nk) ? p : 0.f;
        __syncwarp();
        float* op = g_o + (size_t)m * BHD + hh * HDD;
        float o1 = 0.f, o2 = 0.f;
        for (int t2 = 0; t2 < nk; t2++) {
            float pt = ps[warp][t2];
            const float* vr = vc + (size_t)t2 * BHD + hh * HDD;
            o1 += pt * vr[lane];
            if (lane < 16) o2 += pt * vr[32 + lane];
        }
        op[lane] = o1;
        if (lane < 16) op[32 + lane] = o2;
        __syncwarp();
    }
}

// gen = xi[:, -1]; argmax / EOS / finished logic; write x_out[:, 4+step]
__global__ void gen_k(int Lq, int step) {
    int n = blockIdx.x;
    int t = threadIdx.x;   // 128
    const float* gen = g_xi + (size_t)(n * Lq + Lq - 1) * BHD;
    float bv = -3.402823466e38f;
    int bi = 0;
    for (int c = t; c < BHD; c += 128) {
        float v = gen[c];
        if (v > bv) { bv = v; bi = c; }
    }
    __shared__ float sv[128];
    __shared__ int si[128];
    sv[t] = bv; si[t] = bi;
    __syncthreads();
    for (int s = 64; s > 0; s >>= 1) {
        if (t < s) {
            if (sv[t + s] > sv[t] || (sv[t + s] == sv[t] && si[t + s] < si[t])) {
                sv[t] = sv[t + s]; si[t] = si[t + s];
            }
        }
        __syncthreads();
    }
    __shared__ int unf_s;
    if (t == 0) {
        int fin = g_fin[n];
        unf_s = !fin;
        if (!fin && si[0] == EOS_ID) g_fin[n] = 1;
    }
    __syncthreads();
    int unf = unf_s;
    float* dst = g_xout + (size_t)n * TTOT * BHD + (size_t)(PPRE + step) * BHD;
    for (int c = t; c < BHD; c += 128) dst[c] = unf ? gen[c] : 0.f;
}

// compact x_out[:, P:] into dense (6144,384) in g_t for the LM head
__global__ void compact_k() {
    int m = blockIdx.x;
    int c = threadIdx.x;
    int n = m / SCDEC;
    int tt = m - n * SCDEC;
    g_t[(size_t)m * BHD + c] = g_xout[(size_t)n * TTOT * BHD + (size_t)(PPRE + tt) * BHD + c];
}

// ---------------- launch helpers ----------------
// A: 64x64 (prefill / big M).  B: 32x64 (decode, wide N).  C: 32x32 (decode, N=384).
#define GEMM_A(MODE, A, lda, B, ldb, C, ldc, M, N, K, sh, pos, l) \
    mma_gemm<64, 64, 4, 2, 4, MODE><<<dim3(((N) + 63) / 64, (M) / 64), 256>>>( \
        A, lda, B, ldb, C, ldc, M, N, K, sh, pos, l)

#define GEMM_B(MODE, A, lda, B, ldb, C, ldc, M, N, K, sh, pos, l) \
    mma_gemm<32, 64, 2, 4, 2, MODE><<<dim3(((N) + 63) / 64, (M) / 32), 256>>>( \
        A, lda, B, ldb, C, ldc, M, N, K, sh, pos, l)

#define GEMM_C(MODE, A, lda, B, ldb, C, ldc, M, N, K, sh, pos, l) \
    mma_gemm<32, 32, 2, 4, 1, MODE><<<dim3(((N) + 31) / 32, (M) / 32), 256>>>( \
        A, lda, B, ldb, C, ldc, M, N, K, sh, pos, l)

extern "C" void kernel_launch(void* const* d_in, const int* in_sizes, int n_in,
                              void* d_out, int out_size) {
    (void)in_sizes; (void)n_in; (void)out_size;
    const float* x     = (const float*)d_in[0];
    const float* Wproj = (const float*)d_in[2];
    const float* an    = (const float*)d_in[3];
    const float* Wq    = (const float*)d_in[4];
    const float* Wk    = (const float*)d_in[5];
    const float* Wv    = (const float*)d_in[6];
    const float* Wo    = (const float*)d_in[7];
    const float* fn    = (const float*)d_in[8];
    const float* W1    = (const float*)d_in[9];
    const float* W2    = (const float*)d_in[10];
    const float* Wlm   = (const float*)d_in[11];
    float* out = (float*)d_out;

    float *p_xout, *p_xi, *p_h, *p_o, *p_t, *p_wqkv;
    cudaGetSymbolAddress((void**)&p_xout, g_xout);
    cudaGetSymbolAddress((void**)&p_xi,   g_xi);
    cudaGetSymbolAddress((void**)&p_h,    g_h);
    cudaGetSymbolAddress((void**)&p_o,    g_o);
    cudaGetSymbolAddress((void**)&p_t,    g_t);
    cudaGetSymbolAddress((void**)&p_wqkv, g_wqkv);

    init_fin_k<<<2, 256>>>();
    concat_k<<<(LLAY * BHD * 3 * BHD + 255) / 256, 256>>>(Wq, Wk, Wv);

    // Input projection: (512,1024)@(1024,1536) -> x_out[:, :4, :] (ldc=6144)
    GEMM_A(EPI_STORE, x, HIN, Wproj, FFD, p_xout, TTOT * BHD, NSEQ, FFD, HIN, 0, 0, 0);

    for (int i = 0; i < SCDEC; i++) {
        const int Lq = (i == 0) ? PPRE : 1;
        const int lqShift = (i == 0) ? 2 : 0;
        const int pos = (i == 0) ? 0 : (PPRE + i - 1);
        const int Mrows = NSEQ * Lq;
        const int causal = (i == 0) ? 1 : 0;
        const int total = Mrows * BHD;

        copy_xi_k<<<(total + 255) / 256, 256>>>(Lq, pos, total);

        for (int l = 0; l < LLAY; l++) {
            const float* wqkv_l = p_wqkv + (size_t)l * BHD * 3 * BHD;
            // attn rms
            rms_k<<<Mrows, 128>>>(p_xi, an + l * BHD, p_h);
            // fused QKV GEMM with Q-compact + KV-cache scatter epilogue
            if (i == 0) {
                GEMM_A(EPI_QKV, p_h, BHD, wqkv_l, 3 * BHD, (float*)nullptr, 0,
                       Mrows, 3 * BHD, BHD, lqShift, pos, l);
            } else {
                GEMM_B(EPI_QKV, p_h, BHD, wqkv_l, 3 * BHD, (float*)nullptr, 0,
                       Mrows, 3 * BHD, BHD, lqShift, pos, l);
            }
            // attention
            attn_k<<<NSEQ, 256>>>(l, Lq, pos, causal);
            // o-projection, accumulate into xi
            if (i == 0) {
                GEMM_A(EPI_ACC, p_o, BHD, Wo + (size_t)l * BHD * BHD, BHD,
                       p_xi, BHD, Mrows, BHD, BHD, 0, 0, 0);
            } else {
                GEMM_C(EPI_ACC, p_o, BHD, Wo + (size_t)l * BHD * BHD, BHD,
                       p_xi, BHD, Mrows, BHD, BHD, 0, 0, 0);
            }
            // ffn rms
            rms_k<<<Mrows, 128>>>(p_xi, fn + l * BHD, p_h);
            // FFN1 + exact GELU epilogue
            if (i == 0) {
                GEMM_A(EPI_GELU, p_h, BHD, W1 + (size_t)l * BHD * FFD, FFD,
                       p_t, FFD, Mrows, FFD, BHD, 0, 0, 0);
            } else {
                GEMM_B(EPI_GELU, p_h, BHD, W1 + (size_t)l * BHD * FFD, FFD,
                       p_t, FFD, Mrows, FFD, BHD, 0, 0, 0);
            }
            // FFN2 accumulate into xi
            if (i == 0) {
                GEMM_A(EPI_ACC, p_t, FFD, W2 + (size_t)l * FFD * BHD, BHD,
                       p_xi, BHD, Mrows, BHD, FFD, 0, 0, 0);
            } else {
                GEMM_C(EPI_ACC, p_t, FFD, W2 + (size_t)l * FFD * BHD, BHD,
                       p_xi, BHD, Mrows, BHD, FFD, 0, 0, 0);
            }
        }
        gen_k<<<NSEQ, 128>>>(Lq, i);
    }

    // LM head: compact (6144,384), then @(384,258) -> out
    compact_k<<<NSEQ * SCDEC, BHD>>>();
    GEMM_A(EPI_STORE, p_t, BHD, Wlm, VOC, out, VOC, NSEQ * SCDEC, VOC, BHD, 0, 0, 0);
}

// round 9
// speedup vs baseline: 1.2246x; 1.2246x over previous
#include <cuda_runtime.h>
#include <math.h>
#include <stdint.h>

// Problem constants
#define NSEQ 512       // B*S
#define BHD 384        // BH
#define NHD 8          // heads
#define HDD 48         // head dim
#define TTOT 16        // T = P + S_C
#define PPRE 4         // P
#define SCDEC 12       // S_C
#define LLAY 4         // L
#define VOC 258
#define HIN 1024
#define FFD 1536
#define EOS_ID 257
#define SCALE_F 0.14433756729740643f   // 1/sqrt(48)

// ---------------- scratch (device globals; no runtime allocation) ----------------
__device__ float g_xout[NSEQ * TTOT * BHD];            // (N,16,384)
__device__ float g_kc[LLAY][NSEQ * TTOT * BHD];        // per-layer K cache
__device__ float g_vc[LLAY][NSEQ * TTOT * BHD];        // per-layer V cache
__device__ float g_xi[NSEQ * 4 * BHD];                 // working residual stream
__device__ float g_q[NSEQ * 4 * BHD];                  // compact Q (M,384)
__device__ float g_o[NSEQ * 4 * BHD];                  // attention output
__device__ float g_t[NSEQ * 4 * FFD];                  // ffn intermediate / lm input
__device__ float g_part[4 * NSEQ * BHD];               // split-K partial slabs
__device__ float g_wqkv[LLAY * BHD * 3 * BHD];         // concatenated QKV weights
__device__ int   g_cnt[2048];                          // split-K tile counters
__device__ int   g_fin[NSEQ];

// epilogue modes
#define EPI_STORE 0
#define EPI_ACC   1
#define EPI_GELU  2
#define EPI_QKV   3

__device__ __forceinline__ void qkv_write(int m, int gc, float v, int lqShift, int pos, int layer) {
    int n  = m >> lqShift;
    int qi = m & ((1 << lqShift) - 1);
    if (gc < BHD) {
        g_q[(size_t)m * BHD + gc] = v;
    } else {
        int tp = pos + qi;
        size_t base = ((size_t)n * TTOT + tp) * BHD;
        if (gc < 2 * BHD) g_kc[layer][base + gc - BHD] = v;
        else              g_vc[layer][base + gc - 2 * BHD] = v;
    }
}

__device__ __forceinline__ float gelu_exact(float v) {
    return 0.5f * v * (1.f + erff(v * 0.70710678118654752f));
}

// ================= Kernel 1: RMS-fused GEMM =================
// C[M,N] = rms(A[M,384]) @ B[384,N].  A block (64 x 384) kept fully resident in
// dynamic smem: load once -> per-row rms -> normalize in place -> stream B only.
// 512 threads, tile 64x64, per-thread 4x2.  MODE: EPI_QKV or EPI_GELU.
// Requires: M%64==0, N%64==0, lda%4==0, ldb even.
#define K1_APITCH 392
#define K1_SMEM_FLOATS (64 * K1_APITCH + K1_APITCH + 2 * 16 * 68)
#define K1_SMEM_BYTES  (K1_SMEM_FLOATS * 4)

template<int MODE>
__global__ __launch_bounds__(512) void rms_gemm(
    const float* __restrict__ A, int lda,
    const float* __restrict__ B, int ldb,
    const float* __restrict__ gain,
    float* __restrict__ C, int ldc,
    int lqShift, int pos, int layer)
{
    extern __shared__ float sm[];
    float (*As)[K1_APITCH] = (float(*)[K1_APITCH])sm;
    float* gS = sm + 64 * K1_APITCH;
    float (*Bs)[16][68] = (float(*)[16][68])(sm + 64 * K1_APITCH + K1_APITCH);
    __shared__ float scS[64];

    const int t = threadIdx.x;
    const int m0 = blockIdx.y * 64;
    const int n0 = blockIdx.x * 64;

    if (t < BHD) gS[t] = gain[t];
    // load A block: 64 rows x 384 cols = 6144 float4
    for (int idx = t; idx < 64 * 96; idx += 512) {
        int r = idx / 96, c4 = idx - r * 96;
        *(float4*)&As[r][c4 * 4] =
            *(const float4*)(A + (size_t)(m0 + r) * lda + c4 * 4);
    }
    __syncthreads();

    // per-row rms scale: warp w handles rows w*4 .. w*4+3
    {
        int w = t >> 5, lane = t & 31;
        #pragma unroll
        for (int rr = 0; rr < 4; rr++) {
            int r = w * 4 + rr;
            float s = 0.f;
            for (int j = lane; j < BHD; j += 32) { float v = As[r][j]; s += v * v; }
            #pragma unroll
            for (int o = 16; o > 0; o >>= 1) s += __shfl_xor_sync(0xffffffffu, s, o);
            if (lane == 0) scS[r] = rsqrtf(s * (1.f / (float)BHD) + 1e-5f);
        }
    }
    __syncthreads();
    // normalize in place: As[r][c] *= scale_r * gain_c
    for (int j = t; j < 64 * BHD; j += 512) {
        int r = j / BHD, c = j - r * BHD;
        As[r][c] = As[r][c] * scS[r] * gS[c];
    }

    // B pipeline setup: 512 threads load 16x64 tile (one float2 each)
    const int bk = t >> 5;           // 0..15
    const int bn2 = (t & 31) * 2;    // 0..62
    float2 bReg = *(const float2*)(B + (size_t)bk * ldb + n0 + bn2);
    *(float2*)&Bs[0][bk][bn2] = bReg;
    __syncthreads();

    const int tx = t & 31;           // col group (2 cols)
    const int ty = t >> 5;           // row group (4 rows)
    float acc[4][2] = {};
    int buf = 0;

    #pragma unroll 1
    for (int it = 0; it < 24; ++it) {
        if (it < 23)
            bReg = *(const float2*)(B + (size_t)((it + 1) * 16 + bk) * ldb + n0 + bn2);
        #pragma unroll
        for (int g = 0; g < 4; g++) {
            float4 a4[4];
            #pragma unroll
            for (int r = 0; r < 4; r++)
                a4[r] = *(float4*)&As[ty * 4 + r][it * 16 + g * 4];
            #pragma unroll
            for (int k2 = 0; k2 < 4; k2++) {
                float2 b = *(float2*)&Bs[buf][g * 4 + k2][tx * 2];
                #pragma unroll
                for (int r = 0; r < 4; r++) {
                    float av = ((const float*)&a4[r])[k2];
                    acc[r][0] += av * b.x;
                    acc[r][1] += av * b.y;
                }
            }
        }
        if (it < 23) *(float2*)&Bs[buf ^ 1][bk][bn2] = bReg;
        __syncthreads();
        buf ^= 1;
    }

    // epilogue
    #pragma unroll
    for (int r = 0; r < 4; r++) {
        int row = m0 + ty * 4 + r;
        #pragma unroll
        for (int cj = 0; cj < 2; cj++) {
            int col = n0 + tx * 2 + cj;
            float v = acc[r][cj];
            if (MODE == EPI_QKV) {
                qkv_write(row, col, v, lqShift, pos, layer);
            } else {   // EPI_GELU
                C[(size_t)row * ldc + col] = gelu_exact(v);
            }
        }
    }
}

// ================= Kernel 2: pipelined GEMM (A streamed) =================
// C[M,N] (+)= A[M,K] @ B[K,N].  64x64x16 tiles, 256 threads, 4x4 per thread,
// double-buffered A and B.  gridDim.z = Z split-K with deterministic in-kernel
// reduction (last-arriving block sums partial slabs in fixed z order).
// Requires: M%64==0, (K/Z)%16==0, lda%4==0.  N guarded; ldb may be unaligned.
template<int MODE>
__global__ __launch_bounds__(256) void pipe_gemm(
    const float* __restrict__ A, int lda,
    const float* __restrict__ B, int ldb,
    float* __restrict__ C, int ldc,
    int M, int N, int K,
    float* __restrict__ part, int* __restrict__ cnt)
{
    __shared__ float As[2][64][20];
    __shared__ float Bs[2][16][68];
    const int t = threadIdx.x;
    const int m0 = blockIdx.y * 64;
    const int n0 = blockIdx.x * 64;
    const int Z = gridDim.z;
    const int Kz = K / Z;
    const int kbeg = blockIdx.z * Kz;
    const bool vecB = ((ldb & 3) == 0) && (n0 + 64 <= N);

    const int ar = t >> 2, ak4 = (t & 3) * 4;     // A loader: 1 float4
    const int bk = t >> 4, bn4 = (t & 15) * 4;    // B loader: 1 float4 (or 4 scalar)

    float4 aReg = *(const float4*)(A + (size_t)(m0 + ar) * lda + kbeg + ak4);
    float4 bReg;
    {
        const float* br = B + (size_t)(kbeg + bk) * ldb;
        if (vecB) bReg = *(const float4*)(br + n0 + bn4);
        else {
            bReg.x = (n0 + bn4 + 0 < N) ? br[n0 + bn4 + 0] : 0.f;
            bReg.y = (n0 + bn4 + 1 < N) ? br[n0 + bn4 + 1] : 0.f;
            bReg.z = (n0 + bn4 + 2 < N) ? br[n0 + bn4 + 2] : 0.f;
            bReg.w = (n0 + bn4 + 3 < N) ? br[n0 + bn4 + 3] : 0.f;
        }
    }
    *(float4*)&As[0][ar][ak4] = aReg;
    *(float4*)&Bs[0][bk][bn4] = bReg;
    __syncthreads();

    const int tx = t & 15, ty = t >> 4;
    float acc[4][4] = {};
    const int iters = Kz / 16;
    int buf = 0;

    #pragma unroll 1
    for (int it = 0; it < iters; ++it) {
        if (it + 1 < iters) {
            int k0n = kbeg + (it + 1) * 16;
            aReg = *(const float4*)(A + (size_t)(m0 + ar) * lda + k0n + ak4);
            const float* br = B + (size_t)(k0n + bk) * ldb;
            if (vecB) bReg = *(const float4*)(br + n0 + bn4);
            else {
                bReg.x = (n0 + bn4 + 0 < N) ? br[n0 + bn4 + 0] : 0.f;
                bReg.y = (n0 + bn4 + 1 < N) ? br[n0 + bn4 + 1] : 0.f;
                bReg.z = (n0 + bn4 + 2 < N) ? br[n0 + bn4 + 2] : 0.f;
                bReg.w = (n0 + bn4 + 3 < N) ? br[n0 + bn4 + 3] : 0.f;
            }
        }
        #pragma unroll
        for (int g = 0; g < 4; g++) {
            float4 a4[4];
            #pragma unroll
            for (int r = 0; r < 4; r++)
                a4[r] = *(float4*)&As[buf][ty * 4 + r][g * 4];
            #pragma unroll
            for (int k2 = 0; k2 < 4; k2++) {
                float4 b = *(float4*)&Bs[buf][g * 4 + k2][tx * 4];
                #pragma unroll
                for (int r = 0; r < 4; r++) {
                    float av = ((const float*)&a4[r])[k2];
                    acc[r][0] += av * b.x;
                    acc[r][1] += av * b.y;
                    acc[r][2] += av * b.z;
                    acc[r][3] += av * b.w;
                }
            }
        }
        if (it + 1 < iters) {
            *(float4*)&As[buf ^ 1][ar][ak4] = aReg;
            *(float4*)&Bs[buf ^ 1][bk][bn4] = bReg;
        }
        __syncthreads();
        buf ^= 1;
    }

    if (Z == 1) {
        #pragma unroll
        for (int r = 0; r < 4; r++) {
            int row = m0 + ty * 4 + r;
            #pragma unroll
            for (int c = 0; c < 4; c++) {
                int col = n0 + tx * 4 + c;
                if (col < N) {
                    size_t off = (size_t)row * (size_t)ldc + col;
                    if (MODE == EPI_ACC) C[off] += acc[r][c];
                    else                 C[off] = acc[r][c];
                }
            }
        }
    } else {
        // write partial slab for this z
        float* P = part + (size_t)blockIdx.z * (size_t)M * (size_t)ldc;
        #pragma unroll
        for (int r = 0; r < 4; r++) {
            int row = m0 + ty * 4 + r;
            #pragma unroll
            for (int c = 0; c < 4; c++) {
                int col = n0 + tx * 4 + c;
                if (col < N) P[(size_t)row * ldc + col] = acc[r][c];
            }
        }
        __threadfence();
        __syncthreads();
        __shared__ int sdone;
        const int tile = blockIdx.y * gridDim.x + blockIdx.x;
        if (t == 0) sdone = atomicAdd(&cnt[tile], 1);
        __syncthreads();
        if (sdone == Z - 1) {
            __threadfence();
            for (int idx = t; idx < 64 * 64; idx += 256) {
                int r = idx >> 6, c = idx & 63;
                int col = n0 + c;
                if (col < N) {
                    size_t off = (size_t)(m0 + r) * (size_t)ldc + col;
                    float s = (MODE == EPI_ACC) ? C[off] : 0.f;
                    for (int z = 0; z < Z; z++)
                        s += part[(size_t)z * M * ldc + off];
                    C[off] = s;
                }
            }
            if (t == 0) cnt[tile] = 0;
        }
    }
}

// ---------------- small helper kernels ----------------

__global__ void init_k() {
    int i = blockIdx.x * blockDim.x + threadIdx.x;
    if (i < NSEQ) g_fin[i] = 0;
    if (i < 2048) g_cnt[i] = 0;
}

__global__ void concat_k(const float* __restrict__ Wq,
                         const float* __restrict__ Wk,
                         const float* __restrict__ Wv) {
    int idx = blockIdx.x * blockDim.x + threadIdx.x;
    const int per = BHD * 3 * BHD;
    if (idx >= LLAY * per) return;
    int l = idx / per;
    int r = idx - l * per;
    int k = r / (3 * BHD);
    int j = r - k * (3 * BHD);
    float v;
    int base = l * BHD * BHD + k * BHD;
    if (j < BHD)            v = Wq[base + j];
    else if (j < 2 * BHD)   v = Wk[base + j - BHD];
    else                    v = Wv[base + j - 2 * BHD];
    g_wqkv[idx] = v;
}

// copy xi from x_out
__global__ void copy_xi_k(int Lq, int srcT, int total) {
    int idx = blockIdx.x * blockDim.x + threadIdx.x;
    if (idx >= total) return;
    int m = idx / BHD;
    int c = idx - m * BHD;
    int n = m / Lq;
    int qi = m - n * Lq;
    g_xi[idx] = g_xout[(size_t)n * TTOT * BHD + (size_t)(srcT + qi) * BHD + c];
}

// attention: one block per sequence, 8 warps; warp handles (qi,head) pairs
__global__ void attn_k(int l, int Lq, int pos, int causal) {
    int n = blockIdx.x;
    int warp = threadIdx.x >> 5;
    int lane = threadIdx.x & 31;
    int nk = pos + Lq;
    int npairs = NHD * Lq;
    __shared__ float ps[8][16];
    const float* kc = g_kc[l] + (size_t)n * TTOT * BHD;
    const float* vc = g_vc[l] + (size_t)n * TTOT * BHD;
    for (int pair = warp; pair < npairs; pair += 8) {
        int qi = pair >> 3;
        int hh = pair & 7;
        int m = n * Lq + qi;
        const float* q = g_q + (size_t)m * BHD + hh * HDD;
        float s = -3.402823466e38f;
        if (lane < nk) {
            const float* kr = kc + (size_t)lane * BHD + hh * HDD;
            float a = 0.f;
            #pragma unroll
            for (int d = 0; d < HDD; d++) a += q[d] * kr[d];
            s = a * SCALE_F;
            if (causal && lane > pos + qi) s = -1e30f;
        }
        float mx = s;
        #pragma unroll
        for (int o = 16; o > 0; o >>= 1) mx = fmaxf(mx, __shfl_xor_sync(0xffffffffu, mx, o));
        float e = (lane < nk) ? expf(s - mx) : 0.f;
        float den = e;
        #pragma unroll
        for (int o = 16; o > 0; o >>= 1) den += __shfl_xor_sync(0xffffffffu, den, o);
        float p = e / den;
        if (lane < 16) ps[warp][lane] = (lane < nk) ? p : 0.f;
        __syncwarp();
        float* op = g_o + (size_t)m * BHD + hh * HDD;
        float o1 = 0.f, o2 = 0.f;
        for (int t2 = 0; t2 < nk; t2++) {
            float pt = ps[warp][t2];
            const float* vr = vc + (size_t)t2 * BHD + hh * HDD;
            o1 += pt * vr[lane];
            if (lane < 16) o2 += pt * vr[32 + lane];
        }
        op[lane] = o1;
        if (lane < 16) op[32 + lane] = o2;
        __syncwarp();
    }
}

// gen = xi[:, -1]; argmax / EOS / finished logic; write x_out[:, 4+step]
__global__ void gen_k(int Lq, int step) {
    int n = blockIdx.x;
    int t = threadIdx.x;   // 128
    const float* gen = g_xi + (size_t)(n * Lq + Lq - 1) * BHD;
    float bv = -3.402823466e38f;
    int bi = 0;
    for (int c = t; c < BHD; c += 128) {
        float v = gen[c];
        if (v > bv) { bv = v; bi = c; }
    }
    __shared__ float sv[128];
    __shared__ int si[128];
    sv[t] = bv; si[t] = bi;
    __syncthreads();
    for (int s = 64; s > 0; s >>= 1) {
        if (t < s) {
            if (sv[t + s] > sv[t] || (sv[t + s] == sv[t] && si[t + s] < si[t])) {
                sv[t] = sv[t + s]; si[t] = si[t + s];
            }
        }
        __syncthreads();
    }
    __shared__ int unf_s;
    if (t == 0) {
        int fin = g_fin[n];
        unf_s = !fin;
        if (!fin && si[0] == EOS_ID) g_fin[n] = 1;
    }
    __syncthreads();
    int unf = unf_s;
    float* dst = g_xout + (size_t)n * TTOT * BHD + (size_t)(PPRE + step) * BHD;
    for (int c = t; c < BHD; c += 128) dst[c] = unf ? gen[c] : 0.f;
}

// compact x_out[:, P:] into dense (6144,384) in g_t for the LM head
__global__ void compact_k() {
    int m = blockIdx.x;
    int c = threadIdx.x;
    int n = m / SCDEC;
    int tt = m - n * SCDEC;
    g_t[(size_t)m * BHD + c] = g_xout[(size_t)n * TTOT * BHD + (size_t)(PPRE + tt) * BHD + c];
}

// ---------------- driver ----------------
extern "C" void kernel_launch(void* const* d_in, const int* in_sizes, int n_in,
                              void* d_out, int out_size) {
    (void)in_sizes; (void)n_in; (void)out_size;
    const float* x     = (const float*)d_in[0];
    const float* Wproj = (const float*)d_in[2];
    const float* an    = (const float*)d_in[3];
    const float* Wq    = (const float*)d_in[4];
    const float* Wk    = (const float*)d_in[5];
    const float* Wv    = (const float*)d_in[6];
    const float* Wo    = (const float*)d_in[7];
    const float* fn    = (const float*)d_in[8];
    const float* W1    = (const float*)d_in[9];
    const float* W2    = (const float*)d_in[10];
    const float* Wlm   = (const float*)d_in[11];
    float* out = (float*)d_out;

    float *p_xout, *p_xi, *p_o, *p_t, *p_part, *p_wqkv;
    int *p_cnt;
    cudaGetSymbolAddress((void**)&p_xout, g_xout);
    cudaGetSymbolAddress((void**)&p_xi,   g_xi);
    cudaGetSymbolAddress((void**)&p_o,    g_o);
    cudaGetSymbolAddress((void**)&p_t,    g_t);
    cudaGetSymbolAddress((void**)&p_part, g_part);
    cudaGetSymbolAddress((void**)&p_wqkv, g_wqkv);
    cudaGetSymbolAddress((void**)&p_cnt,  g_cnt);

    // opt-in to large dynamic smem for the RMS-fused GEMM (idempotent, cheap)
    cudaFuncSetAttribute(rms_gemm<EPI_QKV>,
                         cudaFuncAttributeMaxDynamicSharedMemorySize, K1_SMEM_BYTES);
    cudaFuncSetAttribute(rms_gemm<EPI_GELU>,
                         cudaFuncAttributeMaxDynamicSharedMemorySize, K1_SMEM_BYTES);

    init_k<<<8, 256>>>();
    concat_k<<<(LLAY * BHD * 3 * BHD + 255) / 256, 256>>>(Wq, Wk, Wv);

    // Input projection: (512,1024)@(1024,1536) -> x_out[:, :4, :] (ldc=6144)
    pipe_gemm<EPI_STORE><<<dim3(FFD / 64, NSEQ / 64, 1), 256>>>(
        x, HIN, Wproj, FFD, p_xout, TTOT * BHD, NSEQ, FFD, HIN, p_part, p_cnt);

    for (int i = 0; i < SCDEC; i++) {
        const int Lq = (i == 0) ? PPRE : 1;
        const int lqShift = (i == 0) ? 2 : 0;
        const int pos = (i == 0) ? 0 : (PPRE + i - 1);
        const int Mrows = NSEQ * Lq;
        const int causal = (i == 0) ? 1 : 0;
        const int total = Mrows * BHD;
        const int Zdec = (i == 0) ? 1 : 4;   // split-K for decode shapes

        copy_xi_k<<<(total + 255) / 256, 256>>>(Lq, pos, total);

        for (int l = 0; l < LLAY; l++) {
            const float* wqkv_l = p_wqkv + (size_t)l * BHD * 3 * BHD;

            // attn-RMS + QKV GEMM (Q compact + KV cache scatter in epilogue)
            rms_gemm<EPI_QKV><<<dim3(3 * BHD / 64, Mrows / 64), 512, K1_SMEM_BYTES>>>(
                p_xi, BHD, wqkv_l, 3 * BHD, an + l * BHD,
                (float*)nullptr, 0, lqShift, pos, l);

            // attention
            attn_k<<<NSEQ, 256>>>(l, Lq, pos, causal);

            // o-projection: xi += o @ Wo  (split-K for decode)
            pipe_gemm<EPI_ACC><<<dim3(BHD / 64, Mrows / 64, Zdec), 256>>>(
                p_o, BHD, Wo + (size_t)l * BHD * BHD, BHD,
                p_xi, BHD, Mrows, BHD, BHD, p_part, p_cnt);

            // ffn-RMS + FFN1 GEMM + exact GELU epilogue -> g_t
            rms_gemm<EPI_GELU><<<dim3(FFD / 64, Mrows / 64), 512, K1_SMEM_BYTES>>>(
                p_xi, BHD, W1 + (size_t)l * BHD * FFD, FFD, fn + l * BHD,
                p_t, FFD, 0, 0, 0);

            // FFN2: xi += t @ W2  (split-K for decode)
            pipe_gemm<EPI_ACC><<<dim3(BHD / 64, Mrows / 64, Zdec), 256>>>(
                p_t, FFD, W2 + (size_t)l * FFD * BHD, BHD,
                p_xi, BHD, Mrows, BHD, FFD, p_part, p_cnt);
        }
        gen_k<<<NSEQ, 128>>>(Lq, i);
    }

    // LM head: compact (6144,384), then @(384,258) -> out.  N=VOC (R8 bug: was BHD).
    compact_k<<<NSEQ * SCDEC, BHD>>>();
    pipe_gemm<EPI_STORE><<<dim3((VOC + 63) / 64, NSEQ * SCDEC / 64, 1), 256>>>(
        p_t, BHD, Wlm, VOC, out, VOC, NSEQ * SCDEC, VOC, BHD, p_part, p_cnt);
}

// round 12
// speedup vs baseline: 1.2702x; 1.0372x over previous
#include <cuda_runtime.h>
#include <math.h>
#include <stdint.h>

// Problem constants
#define NSEQ 512
#define BHD 384
#define NHD 8
#define HDD 48
#define TTOT 16
#define PPRE 4
#define SCDEC 12
#define LLAY 4
#define VOC 258
#define HIN 1024
#define FFD 1536
#define EOS_ID 257
#define SCALE_F 0.14433756729740643f

#define GRID 296      // 2 CTAs per SM on 148 SMs; co-residency enforced by launch_bounds(256,2)
#define TPB 256

// ---------------- scratch ----------------
__device__ float g_xout[NSEQ * TTOT * BHD];
__device__ float g_kc[LLAY][NSEQ * TTOT * BHD];
__device__ float g_vc[LLAY][NSEQ * TTOT * BHD];
__device__ float g_xi0[NSEQ * PPRE * BHD];      // step-parity buffer A (2048 rows)
__device__ float g_xi1[NSEQ * BHD];             // step-parity buffer B (512 rows)
__device__ float g_h[NSEQ * PPRE * BHD];
__device__ float g_q[NSEQ * PPRE * BHD];
__device__ float g_o[NSEQ * PPRE * BHD];
__device__ float g_t[NSEQ * PPRE * FFD];
__device__ float g_part[2][NSEQ * PPRE * BHD];  // FFN2 split-K partials
__device__ float g_wqkv[LLAY * BHD * 3 * BHD];
__device__ int   g_fin[NSEQ];
__device__ int   g_barC;

// ---------------- grid-wide barrier (counter-based, monotonic) ----------------
__device__ __forceinline__ void gsync(int& barT) {
    barT += GRID;
    __syncthreads();
    if (threadIdx.x == 0) {
        __threadfence();
        atomicAdd(&g_barC, 1);
        while (*(volatile int*)&g_barC < barT) { }
    }
    __syncthreads();
}

__device__ __forceinline__ float gelu_exact(float v) {
    return 0.5f * v * (1.f + erff(v * 0.70710678118654752f));
}

// KV/Q scatter epilogue (L2-coherent stores)
__device__ __forceinline__ void qkv_write(int m, int gc, float v, int lqShift, int pos, int layer) {
    int n  = m >> lqShift;
    int qi = m & ((1 << lqShift) - 1);
    if (gc < BHD) {
        __stcg(&g_q[(size_t)m * BHD + gc], v);
    } else {
        int tp = pos + qi;
        size_t base = ((size_t)n * TTOT + tp) * BHD;
        if (gc < 2 * BHD) __stcg(&g_kc[layer][base + gc - BHD], v);
        else              __stcg(&g_vc[layer][base + gc - 2 * BHD], v);
    }
}

// ---------------- phase: 64x64 tiled GEMM, tile-strided over GRID ----------------
// MODE: 0=store, 2=gelu-store, 3=qkv-scatter.  AMUT: A is mutable (ldcg).
// LMMAP: map A row m -> xout row (m/12)*16 + 4 + m%12.
template<int MODE, bool AMUT, bool LMMAP>
__device__ void ph_gemm64(const float* __restrict__ A, int lda,
                          const float* __restrict__ B, int ldb,
                          float* __restrict__ C, int ldc,
                          int nmt, int nnt, int N, int K,
                          int lqShift, int pos, int layer,
                          float (*As)[64][20], float (*Bs)[16][68]) {
    const int t = threadIdx.x;
    const int ar = t >> 2, ak4 = (t & 3) * 4;
    const int bk = t >> 4, bn4 = (t & 15) * 4;
    const int tx = t & 15, ty = t >> 4;
    const int iters = K / 16;
    for (int tile = blockIdx.x; tile < nmt * nnt; tile += GRID) {
        const int m0 = (tile / nnt) * 64, n0 = (tile % nnt) * 64;
        const bool vecB = ((ldb & 3) == 0) && (n0 + 64 <= N);
        int arow = m0 + ar;
        if (LMMAP) arow = (arow / SCDEC) * TTOT + PPRE + (arow % SCDEC);
        const float* Ap = A + (size_t)arow * lda;

        float4 aReg = AMUT ? __ldcg((const float4*)(Ap + ak4))
                           : *(const float4*)(Ap + ak4);
        float4 bReg;
        {
            const float* br = B + (size_t)bk * ldb;
            if (vecB) bReg = *(const float4*)(br + n0 + bn4);
            else {
                bReg.x = (n0 + bn4 + 0 < N) ? br[n0 + bn4 + 0] : 0.f;
                bReg.y = (n0 + bn4 + 1 < N) ? br[n0 + bn4 + 1] : 0.f;
                bReg.z = (n0 + bn4 + 2 < N) ? br[n0 + bn4 + 2] : 0.f;
                bReg.w = (n0 + bn4 + 3 < N) ? br[n0 + bn4 + 3] : 0.f;
            }
        }
        *(float4*)&As[0][ar][ak4] = aReg;
        *(float4*)&Bs[0][bk][bn4] = bReg;
        __syncthreads();

        float acc[4][4] = {};
        int buf = 0;
        #pragma unroll 1
        for (int it = 0; it < iters; ++it) {
            if (it + 1 < iters) {
                int k0 = (it + 1) * 16;
                aReg = AMUT ? __ldcg((const float4*)(Ap + k0 + ak4))
                            : *(const float4*)(Ap + k0 + ak4);
                const float* br = B + (size_t)(k0 + bk) * ldb;
                if (vecB) bReg = *(const float4*)(br + n0 + bn4);
                else {
                    bReg.x = (n0 + bn4 + 0 < N) ? br[n0 + bn4 + 0] : 0.f;
                    bReg.y = (n0 + bn4 + 1 < N) ? br[n0 + bn4 + 1] : 0.f;
                    bReg.z = (n0 + bn4 + 2 < N) ? br[n0 + bn4 + 2] : 0.f;
                    bReg.w = (n0 + bn4 + 3 < N) ? br[n0 + bn4 + 3] : 0.f;
                }
            }
            #pragma unroll
            for (int g = 0; g < 4; g++) {
                float4 a4[4];
                #pragma unroll
                for (int r = 0; r < 4; r++)
                    a4[r] = *(float4*)&As[buf][ty * 4 + r][g * 4];
                #pragma unroll
                for (int k2 = 0; k2 < 4; k2++) {
                    float4 b = *(float4*)&Bs[buf][g * 4 + k2][tx * 4];
                    #pragma unroll
                    for (int r = 0; r < 4; r++) {
                        float av = ((const float*)&a4[r])[k2];
                        acc[r][0] += av * b.x;
                        acc[r][1] += av * b.y;
                        acc[r][2] += av * b.z;
                        acc[r][3] += av * b.w;
                    }
                }
            }
            if (it + 1 < iters) {
                *(float4*)&As[buf ^ 1][ar][ak4] = aReg;
                *(float4*)&Bs[buf ^ 1][bk][bn4] = bReg;
            }
            __syncthreads();
            buf ^= 1;
        }

        #pragma unroll
        for (int r = 0; r < 4; r++) {
            int row = m0 + ty * 4 + r;
            #pragma unroll
            for (int c = 0; c < 4; c++) {
                int col = n0 + tx * 4 + c;
                float v = acc[r][c];
                if (MODE == 3) {
                    qkv_write(row, col, v, lqShift, pos, layer);
                } else if (col < N) {
                    size_t off = (size_t)row * (size_t)ldc + col;
                    if (MODE == 2) __stcg(&C[off], gelu_exact(v));
                    else           __stcg(&C[off], v);
                }
            }
        }
        __syncthreads();   // protect smem before next tile
    }
}

// ---------------- phase: 32x64 tiled GEMM, N=384 fixed (nnt=6), ldb=ldc=384 ----
// NZ=1: acc into C.  NZ=2: split-K, store partial slab z.
template<int NZ>
__device__ void ph_gemm32(const float* __restrict__ A, int lda,
                          const float* __restrict__ B,
                          float* __restrict__ C,
                          int nmt, int K,
                          float (*As)[64][20], float (*Bs)[16][68]) {
    const int t = threadIdx.x;
    const int kLen = K / NZ, iters = kLen / 16;
    const int ntiles = nmt * 6 * NZ;
    const int ar = t >> 2, ak4 = (t & 3) * 4;   // active t<128
    const int bk = t >> 4, bn4 = (t & 15) * 4;
    const int tx = t & 31, ty = t >> 5;
    for (int tile = blockIdx.x; tile < ntiles; tile += GRID) {
        int z = tile / (nmt * 6);
        int rem = tile - z * (nmt * 6);
        int m0 = (rem / 6) * 32, n0 = (rem % 6) * 64, kOff = z * kLen;
        const float* Ap = A + (size_t)(m0 + ar) * lda + kOff;

        float4 aReg = make_float4(0.f, 0.f, 0.f, 0.f);
        if (t < 128) aReg = __ldcg((const float4*)(Ap + ak4));
        float4 bReg = *(const float4*)(B + (size_t)(kOff + bk) * 384 + n0 + bn4);
        if (t < 128) *(float4*)&As[0][ar][ak4] = aReg;
        *(float4*)&Bs[0][bk][bn4] = bReg;
        __syncthreads();

        float acc[4][2] = {};
        int buf = 0;
        #pragma unroll 1
        for (int it = 0; it < iters; ++it) {
            if (it + 1 < iters) {
                int k0 = (it + 1) * 16;
                if (t < 128) aReg = __ldcg((const float4*)(Ap + k0 + ak4));
                bReg = *(const float4*)(B + (size_t)(kOff + k0 + bk) * 384 + n0 + bn4);
            }
            #pragma unroll
            for (int g = 0; g < 4; g++) {
                float4 a4[4];
                #pragma unroll
                for (int r = 0; r < 4; r++)
                    a4[r] = *(float4*)&As[buf][ty * 4 + r][g * 4];
                #pragma unroll
                for (int k2 = 0; k2 < 4; k2++) {
                    float2 b = *(float2*)&Bs[buf][g * 4 + k2][tx * 2];
                    #pragma unroll
                    for (int r = 0; r < 4; r++) {
                        float av = ((const float*)&a4[r])[k2];
                        acc[r][0] += av * b.x;
                        acc[r][1] += av * b.y;
                    }
                }
            }
            if (it + 1 < iters) {
                if (t < 128) *(float4*)&As[buf ^ 1][ar][ak4] = aReg;
                *(float4*)&Bs[buf ^ 1][bk][bn4] = bReg;
            }
            __syncthreads();
            buf ^= 1;
        }

        #pragma unroll
        for (int r = 0; r < 4; r++) {
            int row = m0 + ty * 4 + r;
            #pragma unroll
            for (int cj = 0; cj < 2; cj++) {
                int col = n0 + tx * 2 + cj;
                size_t off = (size_t)row * 384 + col;
                float v = acc[r][cj];
                if (NZ == 1) __stcg(&C[off], __ldcg(&C[off]) + v);
                else         __stcg(&g_part[z][off], v);
            }
        }
        __syncthreads();
    }
}

// ---------------- small phases ----------------
__device__ void ph_concat(const float* __restrict__ Wq, const float* __restrict__ Wk,
                          const float* __restrict__ Wv) {
    const int per = BHD * 3 * BHD;
    for (int idx = blockIdx.x * TPB + threadIdx.x; idx < LLAY * per; idx += GRID * TPB) {
        int l = idx / per;
        int r = idx - l * per;
        int k = r / (3 * BHD);
        int j = r - k * (3 * BHD);
        int base = l * BHD * BHD + k * BHD;
        float v;
        if (j < BHD)          v = Wq[base + j];
        else if (j < 2 * BHD) v = Wk[base + j - BHD];
        else                  v = Wv[base + j - 2 * BHD];
        g_wqkv[idx] = v;
    }
}

__device__ void ph_copy_xi0() {   // xi0 rows = prefill tokens from xout[:, :4]
    for (int idx = blockIdx.x * TPB + threadIdx.x; idx < NSEQ * PPRE * BHD; idx += GRID * TPB) {
        int n = idx / (PPRE * BHD);
        int rr = idx - n * (PPRE * BHD);
        g_xi0[idx] = __ldcg(&g_xout[(size_t)n * TTOT * BHD + rr]);
    }
}

__device__ void ph_rms(const float* xi, const float* __restrict__ gain, int Mrows) {
    int w = threadIdx.x >> 5, lane = threadIdx.x & 31;
    for (int row = blockIdx.x * 8 + w; row < Mrows; row += GRID * 8) {
        const float* r = xi + (size_t)row * BHD;
        float v[12]; float s = 0.f;
        #pragma unroll
        for (int k = 0; k < 12; k++) { v[k] = __ldcg(&r[k * 32 + lane]); s += v[k] * v[k]; }
        #pragma unroll
        for (int o = 16; o > 0; o >>= 1) s += __shfl_xor_sync(0xffffffffu, s, o);
        float sc = rsqrtf(s * (1.f / (float)BHD) + 1e-5f);
        float* hrow = g_h + (size_t)row * BHD;
        #pragma unroll
        for (int k = 0; k < 12; k++)
            __stcg(&hrow[k * 32 + lane], v[k] * sc * gain[k * 32 + lane]);
    }
}

__device__ void ph_attn(int l, int Lq, int pos, int causal, float (*ps)[16]) {
    int warp = threadIdx.x >> 5;
    int lane = threadIdx.x & 31;
    int nk = pos + Lq;
    int npairs = NHD * Lq;
    for (int n = blockIdx.x; n < NSEQ; n += GRID) {
        const float* kc = g_kc[l] + (size_t)n * TTOT * BHD;
        const float* vc = g_vc[l] + (size_t)n * TTOT * BHD;
        for (int pair = warp; pair < npairs; pair += 8) {
            int qi = pair >> 3;
            int hh = pair & 7;
            int m = n * Lq + qi;
            const float* q = g_q + (size_t)m * BHD + hh * HDD;
            float s = -3.402823466e38f;
            if (lane < nk) {
                const float* kr = kc + (size_t)lane * BHD + hh * HDD;
                float a = 0.f;
                #pragma unroll
                for (int d = 0; d < HDD; d++) a += __ldcg(&q[d]) * __ldcg(&kr[d]);
                s = a * SCALE_F;
                if (causal && lane > pos + qi) s = -1e30f;
            }
            float mx = s;
            #pragma unroll
            for (int o = 16; o > 0; o >>= 1) mx = fmaxf(mx, __shfl_xor_sync(0xffffffffu, mx, o));
            float e = (lane < nk) ? expf(s - mx) : 0.f;
            float den = e;
            #pragma unroll
            for (int o = 16; o > 0; o >>= 1) den += __shfl_xor_sync(0xffffffffu, den, o);
            float p = e / den;
            if (lane < 16) ps[warp][lane] = (lane < nk) ? p : 0.f;
            __syncwarp();
            float* op = g_o + (size_t)m * BHD + hh * HDD;
            float o1 = 0.f, o2 = 0.f;
            for (int t2 = 0; t2 < nk; t2++) {
                float pt = ps[warp][t2];
                const float* vr = vc + (size_t)t2 * BHD + hh * HDD;
                o1 += pt * __ldcg(&vr[lane]);
                if (lane < 16) o2 += pt * __ldcg(&vr[32 + lane]);
            }
            __stcg(&op[lane], o1);
            if (lane < 16) __stcg(&op[32 + lane], o2);
            __syncwarp();
        }
    }
}

__device__ void ph_reduce_ffn2(float* xi, int total) {
    for (int idx = blockIdx.x * TPB + threadIdx.x; idx < total; idx += GRID * TPB)
        __stcg(&xi[idx], __ldcg(&xi[idx]) + __ldcg(&g_part[0][idx]) + __ldcg(&g_part[1][idx]));
}

__device__ void ph_gen(int step, const float* xiCur, float* xiNext) {
    int w = threadIdx.x >> 5, lane = threadIdx.x & 31;
    for (int s = blockIdx.x * 8 + w; s < NSEQ; s += GRID * 8) {
        int srcRow = (step == 0) ? (s * 4 + 3) : s;
        const float* r = xiCur + (size_t)srcRow * BHD;
        float v[12]; float bv = -3.402823466e38f; int bi = 0;
        #pragma unroll
        for (int k = 0; k < 12; k++) {
            v[k] = __ldcg(&r[k * 32 + lane]);
            if (v[k] > bv) { bv = v[k]; bi = k * 32 + lane; }
        }
        #pragma unroll
        for (int o = 16; o > 0; o >>= 1) {
            float vo = __shfl_xor_sync(0xffffffffu, bv, o);
            int   io = __shfl_xor_sync(0xffffffffu, bi, o);
            if (vo > bv || (vo == bv && io < bi)) { bv = vo; bi = io; }
        }
        int fin = (lane == 0) ? g_fin[s] : 0;
        fin = __shfl_sync(0xffffffffu, fin, 0);
        int unf = !fin;
        if (lane == 0 && unf && bi == EOS_ID) g_fin[s] = 1;
        float* xo = g_xout + (size_t)s * TTOT * BHD + (size_t)(PPRE + step) * BHD;
        float* xn = xiNext + (size_t)s * BHD;
        #pragma unroll
        for (int k = 0; k < 12; k++) {
            float val = unf ? v[k] : 0.f;
            __stcg(&xo[k * 32 + lane], val);
            __stcg(&xn[k * 32 + lane], val);
        }
    }
}

// ---------------- the megakernel ----------------
__global__ __launch_bounds__(TPB, 2) void mega(
    const float* __restrict__ x,
    const float* __restrict__ Wproj,
    const float* __restrict__ an,
    const float* __restrict__ Wq,
    const float* __restrict__ Wk,
    const float* __restrict__ Wv,
    const float* __restrict__ Wo,
    const float* __restrict__ fn,
    const float* __restrict__ W1,
    const float* __restrict__ W2,
    const float* __restrict__ Wlm,
    float* __restrict__ out)
{
    __shared__ float shA[2][64][20];
    __shared__ float shB[2][16][68];
    __shared__ float shPs[8][16];
    int barT = 0;

    // weights concat
    ph_concat(Wq, Wk, Wv);
    gsync(barT);

    // input projection: (512,1024)@(1024,1536) -> xout[:, :4, :]
    ph_gemm64<0, false, false>(x, HIN, Wproj, FFD, g_xout, TTOT * BHD,
                               NSEQ / 64, FFD / 64, FFD, HIN, 0, 0, 0, shA, shB);
    gsync(barT);

    ph_copy_xi0();
    gsync(barT);

    for (int step = 0; step < SCDEC; step++) {
        const int Lq = (step == 0) ? PPRE : 1;
        const int lqShift = (step == 0) ? 2 : 0;
        const int pos = (step == 0) ? 0 : (PPRE + step - 1);
        const int causal = (step == 0) ? 1 : 0;
        const int Mrows = NSEQ * Lq;
        float* xiCur  = (step == 0) ? g_xi0 : ((step & 1) ? g_xi1 : g_xi0);
        float* xiNext = (step & 1) ? g_xi0 : g_xi1;

        for (int l = 0; l < LLAY; l++) {
            const float* wqkv_l = g_wqkv + (size_t)l * BHD * 3 * BHD;

            ph_rms(xiCur, an + l * BHD, Mrows);
            gsync(barT);

            ph_gemm64<3, true, false>(g_h, BHD, wqkv_l, 3 * BHD, nullptr, 0,
                                      Mrows / 64, 18, 3 * BHD, BHD,
                                      lqShift, pos, l, shA, shB);
            gsync(barT);

            ph_attn(l, Lq, pos, causal, shPs);
            gsync(barT);

            ph_gemm32<1>(g_o, BHD, Wo + (size_t)l * BHD * BHD, xiCur,
                         Mrows / 32, BHD, shA, shB);
            gsync(barT);

            ph_rms(xiCur, fn + l * BHD, Mrows);
            gsync(barT);

            ph_gemm64<2, true, false>(g_h, BHD, W1 + (size_t)l * BHD * FFD, FFD,
                                      g_t, FFD,
                                      Mrows / 64, 24, FFD, BHD, 0, 0, 0, shA, shB);
            gsync(barT);

            ph_gemm32<2>(g_t, FFD, W2 + (size_t)l * FFD * BHD, nullptr,
                         Mrows / 32, FFD, shA, shB);
            gsync(barT);

            ph_reduce_ffn2(xiCur, Mrows * BHD);
            gsync(barT);
        }

        ph_gen(step, xiCur, xiNext);
        gsync(barT);
    }

    // LM head: rows mapped through xout[:, 4:16], (6144,384)@(384,258) -> out
    ph_gemm64<0, true, true>(g_xout, BHD, Wlm, VOC, out, VOC,
                             (NSEQ * SCDEC) / 64, 5, VOC, BHD, 0, 0, 0, shA, shB);
}

// ---------------- init ----------------
__global__ void init_k() {
    int i = blockIdx.x * blockDim.x + threadIdx.x;
    if (i == 0) g_barC = 0;
    if (i < NSEQ) g_fin[i] = 0;
}

// ---------------- driver ----------------
extern "C" void kernel_launch(void* const* d_in, const int* in_sizes, int n_in,
                              void* d_out, int out_size) {
    (void)in_sizes; (void)n_in; (void)out_size;
    const float* x     = (const float*)d_in[0];
    const float* Wproj = (const float*)d_in[2];
    const float* an    = (const float*)d_in[3];
    const float* Wq    = (const float*)d_in[4];
    const float* Wk    = (const float*)d_in[5];
    const float* Wv    = (const float*)d_in[6];
    const float* Wo    = (const float*)d_in[7];
    const float* fn    = (const float*)d_in[8];
    const float* W1    = (const float*)d_in[9];
    const float* W2    = (const float*)d_in[10];
    const float* Wlm   = (const float*)d_in[11];
    float* out = (float*)d_out;

    init_k<<<2, 256>>>();
    mega<<<GRID, TPB>>>(x, Wproj, an, Wq, Wk, Wv, Wo, fn, W1, W2, Wlm, out);
}